// round 12
// baseline (speedup 1.0000x reference)
#include <cuda_runtime.h>
#include <cuda_bf16.h>
#include <math.h>
#include <stdint.h>

// ---------------- problem constants ----------------
#define BATCH 8
#define SEQ   1024
#define DMODEL 768
#define NHEADS 12
#define DHEAD  64
#define DFF    3072
#define ROWS   (BATCH*SEQ)          // 8192
#define QS     (3*DMODEL)           // 2304 fused qkv row stride
#define LN_EPS 1e-5f

// ---------------- scratch (static device memory; no allocations) ----------------
__device__ float g_qkv[ (size_t)ROWS*QS ];
__device__ float g_ctx[ (size_t)ROWS*DMODEL ];
__device__ float g_prj[ (size_t)ROWS*DMODEL ];
__device__ float g_ln [ (size_t)ROWS*DMODEL ];
__device__ float g_mid[ (size_t)ROWS*DFF ];
__device__ float g_xt [ (size_t)ROWS*DMODEL ];
__device__ float g_wqkvt[ (size_t)QS*DMODEL ];
__device__ float g_bqkv [ QS ];
__device__ float g_wot[ (size_t)DMODEL*DMODEL ];
__device__ float g_w1t[ (size_t)DMODEL*DFF ];
__device__ float g_w2t[ (size_t)DFF*DMODEL ];
__device__ int   g_mask_mode;   // 0 = uint8, 1 = int32, 2 = float32

// ---------------- helpers ----------------
__device__ __forceinline__ uint32_t f2tf32(float x) {
    uint32_t r;
    asm("cvt.rna.tf32.f32 %0, %1;" : "=r"(r) : "f"(x));
    return r;
}
__device__ __forceinline__ float rna(float x) { return __uint_as_float(f2tf32(x)); }

__device__ __forceinline__ void mma_tf32(float* c, const uint32_t* a, const uint32_t* b) {
    asm volatile(
        "mma.sync.aligned.m16n8k8.row.col.f32.tf32.tf32.f32 "
        "{%0,%1,%2,%3}, {%4,%5,%6,%7}, {%8,%9}, {%0,%1,%2,%3};"
        : "+f"(c[0]), "+f"(c[1]), "+f"(c[2]), "+f"(c[3])
        : "r"(a[0]), "r"(a[1]), "r"(a[2]), "r"(a[3]), "r"(b[0]), "r"(b[1]));
}
__device__ __forceinline__ void ldsm4(uint32_t* r, uint32_t addr) {
    asm volatile("ldmatrix.sync.aligned.m8n8.x4.shared.b16 {%0,%1,%2,%3}, [%4];"
                 : "=r"(r[0]), "=r"(r[1]), "=r"(r[2]), "=r"(r[3]) : "r"(addr));
}
__device__ __forceinline__ void cp16(uint32_t dst, const void* src) {
    asm volatile("cp.async.cg.shared.global [%0], [%1], 16;" :: "r"(dst), "l"(src));
}
__device__ __forceinline__ void cp_commit() { asm volatile("cp.async.commit_group;"); }
__device__ __forceinline__ uint32_t smem_u32(const void* p) {
    return (uint32_t)__cvta_generic_to_shared(p);
}

// ---------------- mask dtype detection ----------------
__global__ void detect_mask_kernel(const unsigned char* m) {
    if (threadIdx.x != 0) return;
    int c0 = 0, c1 = 0, c2 = 0, c3 = 0;
    for (int i = 0; i < 4096; i += 4) {
        c0 += (m[i] != 0); c1 += (m[i+1] != 0); c2 += (m[i+2] != 0); c3 += (m[i+3] != 0);
    }
    int mode;
    if (c1 == 0 && c2 == 0 && c3 == 0)      mode = 1;
    else if (c0 == 0 && c1 == 0)            mode = 2;
    else                                     mode = 0;
    g_mask_mode = mode;
}
// two adjacent mask values at element offset base (base is even)
__device__ __forceinline__ void mask2(const void* m, size_t base, int mode,
                                      bool& m0, bool& m1) {
    if (mode == 0) {
        uchar2 u = *(const uchar2*)((const unsigned char*)m + base);
        m0 = u.x != 0; m1 = u.y != 0;
    } else if (mode == 1) {
        int2 u = *(const int2*)((const int*)m + base);
        m0 = u.x != 0; m1 = u.y != 0;
    } else {
        float2 u = *(const float2*)((const float*)m + base);
        m0 = u.x != 0.0f; m1 = u.y != 0.0f;
    }
}

// ---------------- prep ----------------
__global__ void round_tf32_kernel(const float* __restrict__ in, float* __restrict__ out, int n) {
    int i = blockIdx.x * 256 + threadIdx.x;
    int stride = gridDim.x * 256;
    for (; i < n; i += stride) out[i] = rna(in[i]);
}
__global__ void transpose_all_kernel(const float* __restrict__ Wq, const float* __restrict__ Wk,
                                     const float* __restrict__ Wv, const float* __restrict__ Wo,
                                     const float* __restrict__ W1, const float* __restrict__ W2,
                                     float* __restrict__ wqkvt, float* __restrict__ wot,
                                     float* __restrict__ w1t, float* __restrict__ w2t) {
    const float* in; float* out; int R, C;
    switch (blockIdx.z) {
        case 0: in = Wq; out = wqkvt;                              R = DMODEL; C = DMODEL; break;
        case 1: in = Wk; out = wqkvt +   (size_t)DMODEL*DMODEL;    R = DMODEL; C = DMODEL; break;
        case 2: in = Wv; out = wqkvt + 2*(size_t)DMODEL*DMODEL;    R = DMODEL; C = DMODEL; break;
        case 3: in = Wo; out = wot;                                R = DMODEL; C = DMODEL; break;
        case 4: in = W1; out = w1t;                                R = DMODEL; C = DFF;    break;
        default: in = W2; out = w2t;                               R = DFF;    C = DMODEL; break;
    }
    int bx = blockIdx.x * 32, by = blockIdx.y * 32;
    if (bx >= C || by >= R) return;
    __shared__ float t[32][33];
    #pragma unroll
    for (int j = 0; j < 4; j++)
        t[threadIdx.y + j*8][threadIdx.x] =
            in[(size_t)(by + threadIdx.y + j*8) * C + bx + threadIdx.x];
    __syncthreads();
    #pragma unroll
    for (int j = 0; j < 4; j++)
        out[(size_t)(bx + threadIdx.y + j*8) * R + by + threadIdx.x] =
            rna(t[threadIdx.x][threadIdx.y + j*8]);
}
__global__ void pack_bias_kernel(const float* bq, const float* bk, const float* bv, float* out) {
    int i = blockIdx.x * 256 + threadIdx.x;
    if (i < DMODEL) { out[i] = bq[i]; out[DMODEL + i] = bk[i]; out[2*DMODEL + i] = bv[i]; }
}

// ================= tf32 tensor-core GEMM (cp.async + ldmatrix) — unchanged ==========
#define GSA 20

__global__ __launch_bounds__(256, 2)
void gemm_tf32_kernel(const float* __restrict__ A, const float* __restrict__ Bt,
                      const float* __restrict__ bias, float* __restrict__ C,
                      int M, int N, int K, int mode) {
    __shared__ float As[2][128*GSA];
    __shared__ float Bs[2][128*GSA];

    const int tid  = threadIdx.x;
    const int warp = tid >> 5;
    const int lane = tid & 31;
    const int grp  = lane >> 2;
    const int thr  = lane & 3;
    const int wm   = warp >> 2;
    const int wn   = warp & 3;
    const int bm   = blockIdx.y * 128;
    const int bn   = blockIdx.x * 128;

    const int srow = tid >> 2;
    const int skc  = tid & 3;
    const float* gA0 = A  + (size_t)(bm + srow) * K + skc*4;
    const float* gA1 = gA0 + (size_t)64 * K;
    const float* gB0 = Bt + (size_t)(bn + srow) * K + skc*4;
    const float* gB1 = gB0 + (size_t)64 * K;
    const uint32_t as_base = smem_u32(As);
    const uint32_t bs_base = smem_u32(Bs);
    const uint32_t sA0 = (srow*GSA + skc*4) * 4;
    const uint32_t sA1 = sA0 + 64*GSA*4;

    const uint32_t a_off = (lane & 15) * (GSA*4) + ((lane & 16) >> 4) * 16;
    const uint32_t b_off = (lane & 7)  * (GSA*4) + ((lane >> 3) & 3) * 16;

    float acc[4][4][4];
    #pragma unroll
    for (int mi = 0; mi < 4; mi++)
        #pragma unroll
        for (int ni = 0; ni < 4; ni++)
            #pragma unroll
            for (int j = 0; j < 4; j++) acc[mi][ni][j] = 0.0f;

    const int T = K >> 4;
    cp16(as_base + sA0, gA0); cp16(as_base + sA1, gA1);
    cp16(bs_base + sA0, gB0); cp16(bs_base + sA1, gB1);
    cp_commit();

    for (int t = 0; t < T; t++) {
        if (t + 1 < T) {
            int kt = (t + 1) << 4;
            uint32_t ab = as_base + ((t+1)&1) * (128*GSA*4);
            uint32_t bb = bs_base + ((t+1)&1) * (128*GSA*4);
            cp16(ab + sA0, gA0 + kt); cp16(ab + sA1, gA1 + kt);
            cp16(bb + sA0, gB0 + kt); cp16(bb + sA1, gB1 + kt);
            cp_commit();
            asm volatile("cp.async.wait_group 1;");
        } else {
            asm volatile("cp.async.wait_group 0;");
        }
        __syncthreads();

        const uint32_t abase = as_base + (t&1)*(128*GSA*4) + (wm*64)*(GSA*4);
        const uint32_t bbase = bs_base + (t&1)*(128*GSA*4) + (wn*32)*(GSA*4);

        uint32_t bfr[4][4];
        #pragma unroll
        for (int ni = 0; ni < 4; ni++)
            ldsm4(bfr[ni], bbase + ni*8*(GSA*4) + b_off);

        #pragma unroll
        for (int kk = 0; kk < 2; kk++) {
            #pragma unroll
            for (int mi = 0; mi < 4; mi++) {
                uint32_t afr[4];
                ldsm4(afr, abase + mi*16*(GSA*4) + kk*32 + a_off);
                #pragma unroll
                for (int ni = 0; ni < 4; ni++)
                    mma_tf32(acc[mi][ni], afr, &bfr[ni][kk*2]);
            }
        }
        __syncthreads();
    }

    #pragma unroll
    for (int mi = 0; mi < 4; mi++) {
        #pragma unroll
        for (int ni = 0; ni < 4; ni++) {
            int row0 = bm + wm*64 + mi*16 + grp;
            int col  = bn + wn*32 + ni*8 + 2*thr;
            float bz0 = bias[col], bz1 = bias[col + 1];
            float v0 = acc[mi][ni][0] + bz0;
            float v1 = acc[mi][ni][1] + bz1;
            float v2 = acc[mi][ni][2] + bz0;
            float v3 = acc[mi][ni][3] + bz1;
            if (mode == 1) {
                v0 = 0.5f * v0 * (1.0f + erff(v0 * 0.70710678118654752f));
                v1 = 0.5f * v1 * (1.0f + erff(v1 * 0.70710678118654752f));
                v2 = 0.5f * v2 * (1.0f + erff(v2 * 0.70710678118654752f));
                v3 = 0.5f * v3 * (1.0f + erff(v3 * 0.70710678118654752f));
            }
            if (mode != 0) { v0 = rna(v0); v1 = rna(v1); v2 = rna(v2); v3 = rna(v3); }
            *(float2*)(C + (size_t)row0 * N + col)       = make_float2(v0, v1);
            *(float2*)(C + (size_t)(row0 + 8) * N + col) = make_float2(v2, v3);
        }
    }
}

// ================= two-pass streaming tensor-core attention ==========================
// TQ=16 q rows/block, 256 threads (8 warps), 2 CTAs/SM.
// No max subtraction (scores are O(1)): l = sum exp(s); all-masked row -> sentinel -> 1/1024.
// smem: 3 KV pair buffers (K+V, 64x68 each) | P tile 16x68 | lpart 16x8 | linv 16
#define TQ   16
#define KTS  68
#define PTS  68
#define TILE_F (64*KTS)
#define PAIR_F (2*TILE_F)
#define ATTN_SMEM ((3*PAIR_F + TQ*PTS + TQ*8 + TQ) * (int)sizeof(float))

__global__ __launch_bounds__(256, 2)
void attn_kernel(const float* __restrict__ qkv, const void* __restrict__ mask,
                 float* __restrict__ attn, float* __restrict__ ctx) {
    extern __shared__ float sm[];
    float* tiles = sm;                        // 3*PAIR_F
    float* P     = tiles + 3*PAIR_F;          // TQ*PTS
    float* lpart = P + TQ*PTS;                // TQ*8
    float* linv  = lpart + TQ*8;              // TQ

    const float* q = qkv;
    const float* kk = qkv + DMODEL;
    const float* vv = qkv + 2*DMODEL;

    const int qt = blockIdx.x;                // 0..63
    const int bh = blockIdx.y;                // 0..95
    const int b  = bh / NHEADS;
    const int h  = bh % NHEADS;
    const int q0 = qt * TQ;
    const int tid  = threadIdx.x;
    const int warp = tid >> 5;                // 0..7
    const int lane = tid & 31;
    const int grp  = lane >> 2;
    const int thr  = lane & 3;
    const int n0   = warp * 8;
    const int mode = g_mask_mode;

    const uint32_t t0    = smem_u32(tiles);
    const uint32_t pbase = smem_u32(P);
    const uint32_t aT_off = (lane & 15) * (KTS*4) + ((lane & 16) >> 4) * 16;
    const uint32_t b_off  = (lane & 7)  * (KTS*4) + ((lane >> 3) & 3) * 16;
    const uint32_t aP_off = (lane & 15) * (PTS*4) + ((lane & 16) >> 4) * 16;

    // staging: 4 cp16 per thread per 64x64 tile
    const int sr0 = tid >> 4;                 // 0..15
    const int sd  = (tid & 15) * 4;
    const float* ksrc = kk + (size_t)(b*SEQ) * QS + h*DHEAD;
    const float* vsrc = vv + (size_t)(b*SEQ) * QS + h*DHEAD;

    // ---- stage Q (16x64) into tiles[0], hold A fragments ----
    {
        int r = tid >> 4, dd = (tid & 15) * 4;
        *(float4*)&tiles[r*KTS + dd] =
            *(const float4*)&q[(size_t)(b*SEQ + q0 + r) * QS + h*DHEAD + dd];
    }
    __syncthreads();
    uint32_t aq[8][4];
    #pragma unroll
    for (int s = 0; s < 8; s++) ldsm4(aq[s], t0 + s*32 + aT_off);
    __syncthreads();

    // ============ pass 1: l[r] = sum_j exp(s[r][j]) ============
    // prologue: K0 -> pair0.K, K1 -> pair1.K
    #pragma unroll
    for (int pp = 0; pp < 2; pp++) {
        uint32_t db = t0 + pp * (PAIR_F*4);
        const float* src = ksrc + (size_t)(pp*64) * QS;
        #pragma unroll
        for (int i = 0; i < 4; i++) {
            int r = sr0 + i*16;
            cp16(db + (r*KTS + sd)*4, src + (size_t)r*QS + sd);
        }
        cp_commit();
    }

    float l0 = 0.f, l1 = 0.f;
    for (int kt = 0; kt < 16; kt++) {
        if (kt < 15) asm volatile("cp.async.wait_group 1;");
        else         asm volatile("cp.async.wait_group 0;");
        __syncthreads();
        if (kt + 2 < 16) {
            uint32_t db = t0 + ((kt+2)%3) * (PAIR_F*4);
            const float* src = ksrc + (size_t)((kt+2)*64) * QS;
            #pragma unroll
            for (int i = 0; i < 4; i++) {
                int r = sr0 + i*16;
                cp16(db + (r*KTS + sd)*4, src + (size_t)r*QS + sd);
            }
            cp_commit();
        }

        const uint32_t tb = t0 + (kt%3) * (PAIR_F*4);
        uint32_t bk[4][4];
        #pragma unroll
        for (int g = 0; g < 4; g++)
            ldsm4(bk[g], tb + n0*(KTS*4) + g*64 + b_off);
        float c4[4] = {0.f, 0.f, 0.f, 0.f};
        #pragma unroll
        for (int s = 0; s < 8; s++)
            mma_tf32(c4, aq[s], &bk[s >> 1][(s & 1) * 2]);

        int col = n0 + 2*thr;
        int gk  = kt*64 + col;
        bool ma0, ma1, mb0, mb1;
        mask2(mask, (size_t)(b*SEQ + q0 + grp) * SEQ + gk,     mode, ma0, ma1);
        mask2(mask, (size_t)(b*SEQ + q0 + grp + 8) * SEQ + gk, mode, mb0, mb1);
        float s0 = ma0 ? -1e9f : c4[0] * 0.125f;
        float s1 = ma1 ? -1e9f : c4[1] * 0.125f;
        float s2 = mb0 ? -1e9f : c4[2] * 0.125f;
        float s3 = mb1 ? -1e9f : c4[3] * 0.125f;
        l0 += __expf(s0) + __expf(s1);
        l1 += __expf(s2) + __expf(s3);
    }

    // reduce l across thr lanes (quad) then across 8 warps
    l0 += __shfl_xor_sync(0xffffffffu, l0, 1);
    l0 += __shfl_xor_sync(0xffffffffu, l0, 2);
    l1 += __shfl_xor_sync(0xffffffffu, l1, 1);
    l1 += __shfl_xor_sync(0xffffffffu, l1, 2);
    if (thr == 0) {
        lpart[grp*8 + warp]     = l0;
        lpart[(grp+8)*8 + warp] = l1;
    }
    __syncthreads();
    if (tid < TQ) {
        float s = 0.f;
        #pragma unroll
        for (int w = 0; w < 8; w++) s += lpart[tid*8 + w];
        linv[tid] = (s == 0.f) ? -1.f : 1.0f / s;   // -1 = all-masked sentinel
    }
    __syncthreads();

    const float iv0 = linv[grp];
    const float iv1 = linv[grp + 8];

    // ============ pass 2: recompute p, write attn, accumulate P@V ============
    // prologue: pairs 0,1 (K+V each)
    #pragma unroll
    for (int pp = 0; pp < 2; pp++) {
        uint32_t db = t0 + pp * (PAIR_F*4);
        const float* ks = ksrc + (size_t)(pp*64) * QS;
        const float* vs = vsrc + (size_t)(pp*64) * QS;
        #pragma unroll
        for (int i = 0; i < 4; i++) {
            int r = sr0 + i*16;
            cp16(db + (r*KTS + sd)*4,              ks + (size_t)r*QS + sd);
            cp16(db + (TILE_F + r*KTS + sd)*4,     vs + (size_t)r*QS + sd);
        }
        cp_commit();
    }

    float cc[4] = {0.f, 0.f, 0.f, 0.f};
    float* adst = attn ? attn + ((size_t)(b*NHEADS + h) * SEQ + q0) * SEQ : nullptr;

    for (int kt = 0; kt < 16; kt++) {
        if (kt < 15) asm volatile("cp.async.wait_group 1;");
        else         asm volatile("cp.async.wait_group 0;");
        __syncthreads();   // pair kt ready; prev P fully consumed
        if (kt + 2 < 16) {
            uint32_t db = t0 + ((kt+2)%3) * (PAIR_F*4);
            const float* ks = ksrc + (size_t)((kt+2)*64) * QS;
            const float* vs = vsrc + (size_t)((kt+2)*64) * QS;
            #pragma unroll
            for (int i = 0; i < 4; i++) {
                int r = sr0 + i*16;
                cp16(db + (r*KTS + sd)*4,          ks + (size_t)r*QS + sd);
                cp16(db + (TILE_F + r*KTS + sd)*4, vs + (size_t)r*QS + sd);
            }
            cp_commit();
        }

        const uint32_t tb = t0 + (kt%3) * (PAIR_F*4);
        uint32_t bk[4][4];
        #pragma unroll
        for (int g = 0; g < 4; g++)
            ldsm4(bk[g], tb + n0*(KTS*4) + g*64 + b_off);
        float c4[4] = {0.f, 0.f, 0.f, 0.f};
        #pragma unroll
        for (int s = 0; s < 8; s++)
            mma_tf32(c4, aq[s], &bk[s >> 1][(s & 1) * 2]);

        int col = n0 + 2*thr;
        int gk  = kt*64 + col;
        bool ma0, ma1, mb0, mb1;
        mask2(mask, (size_t)(b*SEQ + q0 + grp) * SEQ + gk,     mode, ma0, ma1);
        mask2(mask, (size_t)(b*SEQ + q0 + grp + 8) * SEQ + gk, mode, mb0, mb1);
        float s0 = ma0 ? -1e9f : c4[0] * 0.125f;
        float s1 = ma1 ? -1e9f : c4[1] * 0.125f;
        float s2 = mb0 ? -1e9f : c4[2] * 0.125f;
        float s3 = mb1 ? -1e9f : c4[3] * 0.125f;
        const float UNI = 0.0009765625f;  // 1/1024 (all-masked row)
        float p0 = (iv0 < 0.f) ? UNI : __expf(s0) * iv0;
        float p1 = (iv0 < 0.f) ? UNI : __expf(s1) * iv0;
        float p2 = (iv1 < 0.f) ? UNI : __expf(s2) * iv1;
        float p3 = (iv1 < 0.f) ? UNI : __expf(s3) * iv1;
        *(float2*)&P[grp*PTS + col]     = make_float2(p0, p1);
        *(float2*)&P[(grp+8)*PTS + col] = make_float2(p2, p3);
        __syncthreads();   // P ready

        // write attn tile (coalesced from smem)
        if (adst) {
            int r = tid >> 4, dd = (tid & 15) * 4;
            *(float4*)&adst[(size_t)r * SEQ + kt*64 + dd] = *(float4*)&P[r*PTS + dd];
        }

        // P @ V for this tile (V in tb + TILE_F)
        const float* vbuf = tiles + (kt%3)*PAIR_F + TILE_F;
        #pragma unroll
        for (int g = 0; g < 4; g++) {
            uint32_t ap0[4], ap1[4];
            ldsm4(ap0, pbase + (g*16)     * 4 + aP_off);
            ldsm4(ap1, pbase + (g*16 + 8) * 4 + aP_off);
            int kloc0 = g*16;
            uint32_t bv0[2], bv1[2];
            bv0[0] = __float_as_uint(vbuf[(kloc0 + thr    )*KTS + n0 + grp]);
            bv0[1] = __float_as_uint(vbuf[(kloc0 + thr + 4)*KTS + n0 + grp]);
            bv1[0] = __float_as_uint(vbuf[(kloc0 + 8 + thr    )*KTS + n0 + grp]);
            bv1[1] = __float_as_uint(vbuf[(kloc0 + 8 + thr + 4)*KTS + n0 + grp]);
            mma_tf32(cc, ap0, bv0);
            mma_tf32(cc, ap1, bv1);
        }
    }

    {
        int dc = h*DHEAD + n0 + 2*thr;
        *(float2*)&ctx[(size_t)(b*SEQ + q0 + grp) * DMODEL + dc] =
            make_float2(rna(cc[0]), rna(cc[1]));
        *(float2*)&ctx[(size_t)(b*SEQ + q0 + grp + 8) * DMODEL + dc] =
            make_float2(rna(cc[2]), rna(cc[3]));
    }
}

// ---------------- residual + LayerNorm (tf32-rounded out; feeds FFN1) ----------------
__global__ __launch_bounds__(256)
void ln_kernel(const float* __restrict__ proj, const float* __restrict__ x,
               const float* __restrict__ gamma, const float* __restrict__ beta,
               float* __restrict__ out) {
    const int row = blockIdx.x;
    const float* p  = proj + (size_t)row * DMODEL;
    const float* xr = x    + (size_t)row * DMODEL;
    float s = 0.f, s2 = 0.f;
    for (int i = threadIdx.x; i < DMODEL; i += 256) {
        float v = p[i] + xr[i];
        s += v; s2 += v*v;
    }
    #pragma unroll
    for (int m = 16; m; m >>= 1) {
        s  += __shfl_xor_sync(0xffffffffu, s,  m);
        s2 += __shfl_xor_sync(0xffffffffu, s2, m);
    }
    __shared__ float ws[8], ws2[8];
    int w = threadIdx.x >> 5, l = threadIdx.x & 31;
    if (l == 0) { ws[w] = s; ws2[w] = s2; }
    __syncthreads();
    __shared__ float smu, srstd;
    if (threadIdx.x == 0) {
        float ts = 0.f, ts2 = 0.f;
        for (int i = 0; i < 8; i++) { ts += ws[i]; ts2 += ws2[i]; }
        float mu  = ts  * (1.0f/DMODEL);
        float var = ts2 * (1.0f/DMODEL) - mu*mu;
        smu = mu; srstd = rsqrtf(var + LN_EPS);
    }
    __syncthreads();
    float mu = smu, r = srstd;
    float* o = out + (size_t)row * DMODEL;
    for (int i = threadIdx.x; i < DMODEL; i += 256)
        o[i] = rna((p[i] + xr[i] - mu) * r * gamma[i] + beta[i]);
}

// ---------------- launcher ----------------
extern "C" void kernel_launch(void* const* d_in, const int* in_sizes, int n_in,
                              void* d_out, int out_size) {
    const float* x     = (const float*)d_in[0];
    const void*  mask  = d_in[1];
    const float* Wq    = (const float*)d_in[2];
    const float* bq    = (const float*)d_in[3];
    const float* Wk    = (const float*)d_in[4];
    const float* bk    = (const float*)d_in[5];
    const float* Wv    = (const float*)d_in[6];
    const float* bv    = (const float*)d_in[7];
    const float* Wo    = (const float*)d_in[8];
    const float* bo    = (const float*)d_in[9];
    const float* gamma = (const float*)d_in[10];
    const float* beta  = (const float*)d_in[11];
    const float* W1    = (const float*)d_in[12];
    const float* b1    = (const float*)d_in[13];
    const float* W2    = (const float*)d_in[14];
    const float* b2    = (const float*)d_in[15];

    float* out = (float*)d_out;
    const long long FFN_E  = (long long)ROWS * DMODEL;
    const long long ATTN_E = (long long)BATCH * NHEADS * SEQ * SEQ;
    float* attn = ((long long)out_size >= FFN_E + ATTN_E) ? (out + FFN_E) : nullptr;

    float *qkv, *ctx, *prj, *ln, *mid, *xt, *wqkvt, *bqkv, *wot, *w1t, *w2t;
    cudaGetSymbolAddress((void**)&qkv,   g_qkv);
    cudaGetSymbolAddress((void**)&ctx,   g_ctx);
    cudaGetSymbolAddress((void**)&prj,   g_prj);
    cudaGetSymbolAddress((void**)&ln,    g_ln);
    cudaGetSymbolAddress((void**)&mid,   g_mid);
    cudaGetSymbolAddress((void**)&xt,    g_xt);
    cudaGetSymbolAddress((void**)&wqkvt, g_wqkvt);
    cudaGetSymbolAddress((void**)&bqkv,  g_bqkv);
    cudaGetSymbolAddress((void**)&wot,   g_wot);
    cudaGetSymbolAddress((void**)&w1t,   g_w1t);
    cudaGetSymbolAddress((void**)&w2t,   g_w2t);

    cudaFuncSetAttribute(attn_kernel, cudaFuncAttributeMaxDynamicSharedMemorySize, ATTN_SMEM);

    // launches 1-5 before attention (ncu -s 5 -c 1 captures attn)
    detect_mask_kernel<<<1, 32>>>((const unsigned char*)mask);
    round_tf32_kernel<<<1024, 256>>>(x, xt, ROWS*DMODEL);
    transpose_all_kernel<<<dim3(96, 96, 6), dim3(32, 8)>>>(Wq, Wk, Wv, Wo, W1, W2,
                                                           wqkvt, wot, w1t, w2t);
    pack_bias_kernel<<<3, 256>>>(bq, bk, bv, bqkv);
    gemm_tf32_kernel<<<dim3(QS/128, ROWS/128), 256>>>(xt, wqkvt, bqkv, qkv, ROWS, QS, DMODEL, 2);

    attn_kernel<<<dim3(SEQ/TQ, BATCH*NHEADS), 256, ATTN_SMEM>>>(qkv, mask, attn, ctx);

    gemm_tf32_kernel<<<dim3(DMODEL/128, ROWS/128), 256>>>(ctx, wot, bo, prj, ROWS, DMODEL, DMODEL, 0);
    ln_kernel<<<ROWS, 256>>>(prj, x, gamma, beta, ln);

    gemm_tf32_kernel<<<dim3(DFF/128, ROWS/128), 256>>>(ln, w1t, b1, mid, ROWS, DFF, DMODEL, 1);
    gemm_tf32_kernel<<<dim3(DMODEL/128, ROWS/128), 256>>>(mid, w2t, b2, out, ROWS, DMODEL, DFF, 0);
}

// round 13
// speedup vs baseline: 1.1453x; 1.1453x over previous
#include <cuda_runtime.h>
#include <cuda_bf16.h>
#include <math.h>
#include <stdint.h>

// ---------------- problem constants ----------------
#define BATCH 8
#define SEQ   1024
#define DMODEL 768
#define NHEADS 12
#define DHEAD  64
#define DFF    3072
#define ROWS   (BATCH*SEQ)          // 8192
#define QS     (3*DMODEL)           // 2304 fused qkv row stride
#define LN_EPS 1e-5f

// ---------------- scratch (static device memory; no allocations) ----------------
__device__ float g_qkv[ (size_t)ROWS*QS ];
__device__ float g_ctx[ (size_t)ROWS*DMODEL ];
__device__ float g_prj[ (size_t)ROWS*DMODEL ];
__device__ float g_ln [ (size_t)ROWS*DMODEL ];
__device__ float g_mid[ (size_t)ROWS*DFF ];
__device__ float g_xt [ (size_t)ROWS*DMODEL ];
__device__ float g_wqkvt[ (size_t)QS*DMODEL ];
__device__ float g_bqkv [ QS ];
__device__ float g_wot[ (size_t)DMODEL*DMODEL ];
__device__ float g_w1t[ (size_t)DMODEL*DFF ];
__device__ float g_w2t[ (size_t)DFF*DMODEL ];
__device__ int   g_mask_mode;   // 0 = uint8, 1 = int32, 2 = float32

// ---------------- helpers ----------------
__device__ __forceinline__ uint32_t f2tf32(float x) {
    uint32_t r;
    asm("cvt.rna.tf32.f32 %0, %1;" : "=r"(r) : "f"(x));
    return r;
}
__device__ __forceinline__ float rna(float x) { return __uint_as_float(f2tf32(x)); }

__device__ __forceinline__ void mma_tf32(float* c, const uint32_t* a, const uint32_t* b) {
    asm volatile(
        "mma.sync.aligned.m16n8k8.row.col.f32.tf32.tf32.f32 "
        "{%0,%1,%2,%3}, {%4,%5,%6,%7}, {%8,%9}, {%0,%1,%2,%3};"
        : "+f"(c[0]), "+f"(c[1]), "+f"(c[2]), "+f"(c[3])
        : "r"(a[0]), "r"(a[1]), "r"(a[2]), "r"(a[3]), "r"(b[0]), "r"(b[1]));
}
__device__ __forceinline__ void ldsm4(uint32_t* r, uint32_t addr) {
    asm volatile("ldmatrix.sync.aligned.m8n8.x4.shared.b16 {%0,%1,%2,%3}, [%4];"
                 : "=r"(r[0]), "=r"(r[1]), "=r"(r[2]), "=r"(r[3]) : "r"(addr));
}
__device__ __forceinline__ void cp16(uint32_t dst, const void* src) {
    asm volatile("cp.async.cg.shared.global [%0], [%1], 16;" :: "r"(dst), "l"(src));
}
__device__ __forceinline__ void cp_commit() { asm volatile("cp.async.commit_group;"); }
__device__ __forceinline__ uint32_t smem_u32(const void* p) {
    return (uint32_t)__cvta_generic_to_shared(p);
}

// ---------------- mask dtype detection ----------------
__global__ void detect_mask_kernel(const unsigned char* m) {
    if (threadIdx.x != 0) return;
    int c0 = 0, c1 = 0, c2 = 0, c3 = 0;
    for (int i = 0; i < 4096; i += 4) {
        c0 += (m[i] != 0); c1 += (m[i+1] != 0); c2 += (m[i+2] != 0); c3 += (m[i+3] != 0);
    }
    int mode;
    if (c1 == 0 && c2 == 0 && c3 == 0)      mode = 1;
    else if (c0 == 0 && c1 == 0)            mode = 2;
    else                                     mode = 0;
    g_mask_mode = mode;
}
// two adjacent mask values at element offset base (base is even)
__device__ __forceinline__ void mask2(const void* m, size_t base, int mode,
                                      bool& m0, bool& m1) {
    if (mode == 0) {
        uchar2 u = *(const uchar2*)((const unsigned char*)m + base);
        m0 = u.x != 0; m1 = u.y != 0;
    } else if (mode == 1) {
        int2 u = *(const int2*)((const int*)m + base);
        m0 = u.x != 0; m1 = u.y != 0;
    } else {
        float2 u = *(const float2*)((const float*)m + base);
        m0 = u.x != 0.0f; m1 = u.y != 0.0f;
    }
}

// ---------------- prep ----------------
__global__ void round_tf32_kernel(const float* __restrict__ in, float* __restrict__ out, int n) {
    int i = blockIdx.x * 256 + threadIdx.x;
    int stride = gridDim.x * 256;
    for (; i < n; i += stride) out[i] = rna(in[i]);
}
__global__ void transpose_all_kernel(const float* __restrict__ Wq, const float* __restrict__ Wk,
                                     const float* __restrict__ Wv, const float* __restrict__ Wo,
                                     const float* __restrict__ W1, const float* __restrict__ W2,
                                     float* __restrict__ wqkvt, float* __restrict__ wot,
                                     float* __restrict__ w1t, float* __restrict__ w2t) {
    const float* in; float* out; int R, C;
    switch (blockIdx.z) {
        case 0: in = Wq; out = wqkvt;                              R = DMODEL; C = DMODEL; break;
        case 1: in = Wk; out = wqkvt +   (size_t)DMODEL*DMODEL;    R = DMODEL; C = DMODEL; break;
        case 2: in = Wv; out = wqkvt + 2*(size_t)DMODEL*DMODEL;    R = DMODEL; C = DMODEL; break;
        case 3: in = Wo; out = wot;                                R = DMODEL; C = DMODEL; break;
        case 4: in = W1; out = w1t;                                R = DMODEL; C = DFF;    break;
        default: in = W2; out = w2t;                               R = DFF;    C = DMODEL; break;
    }
    int bx = blockIdx.x * 32, by = blockIdx.y * 32;
    if (bx >= C || by >= R) return;
    __shared__ float t[32][33];
    #pragma unroll
    for (int j = 0; j < 4; j++)
        t[threadIdx.y + j*8][threadIdx.x] =
            in[(size_t)(by + threadIdx.y + j*8) * C + bx + threadIdx.x];
    __syncthreads();
    #pragma unroll
    for (int j = 0; j < 4; j++)
        out[(size_t)(bx + threadIdx.y + j*8) * R + by + threadIdx.x] =
            rna(t[threadIdx.x][threadIdx.y + j*8]);
}
__global__ void pack_bias_kernel(const float* bq, const float* bk, const float* bv, float* out) {
    int i = blockIdx.x * 256 + threadIdx.x;
    if (i < DMODEL) { out[i] = bq[i]; out[DMODEL + i] = bk[i]; out[2*DMODEL + i] = bv[i]; }
}

// ================= tf32 tensor-core GEMM: cp.async 3-stage ring + ldmatrix ===========
// C[M,N] = A[M,K] @ Bt[N,K]^T + bias.  A,Bt pre-rounded tf32 values.
// mode: 0 = fp32 out, 1 = exact GELU + tf32 round, 2 = tf32 round.
#define GSA 20   // smem row stride in floats (80B)
#define STG 3    // pipeline stages (prefetch distance 2)

__global__ __launch_bounds__(256, 2)
void gemm_tf32_kernel(const float* __restrict__ A, const float* __restrict__ Bt,
                      const float* __restrict__ bias, float* __restrict__ C,
                      int M, int N, int K, int mode) {
    __shared__ float As[STG][128*GSA];
    __shared__ float Bs[STG][128*GSA];

    const int tid  = threadIdx.x;
    const int warp = tid >> 5;
    const int lane = tid & 31;
    const int grp  = lane >> 2;
    const int thr  = lane & 3;
    const int wm   = warp >> 2;
    const int wn   = warp & 3;
    const int bm   = blockIdx.y * 128;
    const int bn   = blockIdx.x * 128;

    const int srow = tid >> 2;
    const int skc  = tid & 3;
    const float* gA0 = A  + (size_t)(bm + srow) * K + skc*4;
    const float* gA1 = gA0 + (size_t)64 * K;
    const float* gB0 = Bt + (size_t)(bn + srow) * K + skc*4;
    const float* gB1 = gB0 + (size_t)64 * K;
    const uint32_t as_base = smem_u32(As);
    const uint32_t bs_base = smem_u32(Bs);
    const uint32_t sA0 = (srow*GSA + skc*4) * 4;
    const uint32_t sA1 = sA0 + 64*GSA*4;

    const uint32_t a_off = (lane & 15) * (GSA*4) + ((lane & 16) >> 4) * 16;
    const uint32_t b_off = (lane & 7)  * (GSA*4) + ((lane >> 3) & 3) * 16;

    float acc[4][4][4];
    #pragma unroll
    for (int mi = 0; mi < 4; mi++)
        #pragma unroll
        for (int ni = 0; ni < 4; ni++)
            #pragma unroll
            for (int j = 0; j < 4; j++) acc[mi][ni][j] = 0.0f;

    const int T = K >> 4;
    // prologue: stage tiles 0 and 1 into buffers 0,1 (one commit group each)
    #pragma unroll
    for (int p = 0; p < 2; p++) {
        int kt = p << 4;
        uint32_t ab = as_base + p * (128*GSA*4);
        uint32_t bb = bs_base + p * (128*GSA*4);
        cp16(ab + sA0, gA0 + kt); cp16(ab + sA1, gA1 + kt);
        cp16(bb + sA0, gB0 + kt); cp16(bb + sA1, gB1 + kt);
        cp_commit();
    }

    for (int t = 0; t < T; t++) {
        if (t + 2 < T) {
            int kt = (t + 2) << 4;
            int buf = (t + 2) % STG;
            uint32_t ab = as_base + buf * (128*GSA*4);
            uint32_t bb = bs_base + buf * (128*GSA*4);
            cp16(ab + sA0, gA0 + kt); cp16(ab + sA1, gA1 + kt);
            cp16(bb + sA0, gB0 + kt); cp16(bb + sA1, gB1 + kt);
            cp_commit();
            asm volatile("cp.async.wait_group 2;");
        } else if (t + 1 < T) {
            asm volatile("cp.async.wait_group 1;");
        } else {
            asm volatile("cp.async.wait_group 0;");
        }
        __syncthreads();

        const int buf = t % STG;
        const uint32_t abase = as_base + buf*(128*GSA*4) + (wm*64)*(GSA*4);
        const uint32_t bbase = bs_base + buf*(128*GSA*4) + (wn*32)*(GSA*4);

        uint32_t bfr[4][4];
        #pragma unroll
        for (int ni = 0; ni < 4; ni++)
            ldsm4(bfr[ni], bbase + ni*8*(GSA*4) + b_off);

        #pragma unroll
        for (int kk = 0; kk < 2; kk++) {
            #pragma unroll
            for (int mi = 0; mi < 4; mi++) {
                uint32_t afr[4];
                ldsm4(afr, abase + mi*16*(GSA*4) + kk*32 + a_off);
                #pragma unroll
                for (int ni = 0; ni < 4; ni++)
                    mma_tf32(acc[mi][ni], afr, &bfr[ni][kk*2]);
            }
        }
        __syncthreads();
    }

    #pragma unroll
    for (int mi = 0; mi < 4; mi++) {
        #pragma unroll
        for (int ni = 0; ni < 4; ni++) {
            int row0 = bm + wm*64 + mi*16 + grp;
            int col  = bn + wn*32 + ni*8 + 2*thr;
            float bz0 = bias[col], bz1 = bias[col + 1];
            float v0 = acc[mi][ni][0] + bz0;
            float v1 = acc[mi][ni][1] + bz1;
            float v2 = acc[mi][ni][2] + bz0;
            float v3 = acc[mi][ni][3] + bz1;
            if (mode == 1) {
                v0 = 0.5f * v0 * (1.0f + erff(v0 * 0.70710678118654752f));
                v1 = 0.5f * v1 * (1.0f + erff(v1 * 0.70710678118654752f));
                v2 = 0.5f * v2 * (1.0f + erff(v2 * 0.70710678118654752f));
                v3 = 0.5f * v3 * (1.0f + erff(v3 * 0.70710678118654752f));
            }
            if (mode != 0) { v0 = rna(v0); v1 = rna(v1); v2 = rna(v2); v3 = rna(v3); }
            *(float2*)(C + (size_t)row0 * N + col)       = make_float2(v0, v1);
            *(float2*)(C + (size_t)(row0 + 8) * N + col) = make_float2(v2, v3);
        }
    }
}

// ================= tensor-core attention (R10 version: TQ=32, 512 thr, pipelined) ====
// smem: scores[32][1028] | 3 x tile[64][68] | sinv[32]
#define TQ  32
#define SCS 1028
#define KTS 68
#define TILE_F (64*KTS)
#define ATTN_SMEM ((TQ*SCS + 3*TILE_F + TQ) * (int)sizeof(float))

__global__ __launch_bounds__(512, 1)
void attn_kernel(const float* __restrict__ qkv, const void* __restrict__ mask,
                 float* __restrict__ attn, float* __restrict__ ctx) {
    extern __shared__ float sm[];
    float* scores = sm;                       // TQ*SCS
    float* tiles  = scores + TQ*SCS;          // 3 * TILE_F
    float* sinv   = tiles + 3*TILE_F;         // TQ

    const float* q = qkv;
    const float* k = qkv + DMODEL;
    const float* v = qkv + 2*DMODEL;

    const int qt = blockIdx.x;
    const int bh = blockIdx.y;
    const int b  = bh / NHEADS;
    const int h  = bh % NHEADS;
    const int q0 = qt * TQ;
    const int tid  = threadIdx.x;
    const int warp = tid >> 5;                // 0..15
    const int lane = tid & 31;
    const int grp  = lane >> 2;
    const int thr  = lane & 3;
    const int qh   = warp >> 3;               // 0/1
    const int n0   = (warp & 7) * 8;
    const int mode = g_mask_mode;

    const uint32_t t0    = smem_u32(tiles);
    const uint32_t sbase = smem_u32(scores);
    const uint32_t aT_off = (lane & 15) * (KTS*4) + ((lane & 16) >> 4) * 16;
    const uint32_t b_off  = (lane & 7)  * (KTS*4) + ((lane >> 3) & 3) * 16;
    const uint32_t aS_off = (lane & 15) * (SCS*4) + ((lane & 16) >> 4) * 16;

    const int sr0 = tid >> 4;                 // 0..31
    const int sd  = (tid & 15) * 4;

    // ---- stage Q (32x64) into buffer 0, hold A fragments in regs ----
    {
        int r = tid >> 4, dd = (tid & 15) * 4;
        *(float4*)&tiles[r*KTS + dd] =
            *(const float4*)&q[(size_t)(b*SEQ + q0 + r) * QS + h*DHEAD + dd];
    }
    __syncthreads();
    uint32_t aq[8][4];
    #pragma unroll
    for (int s = 0; s < 8; s++)
        ldsm4(aq[s], t0 + (qh*16)*(KTS*4) + s*32 + aT_off);
    __syncthreads();

    // ---- phase 1: scores = QK^T/8 + inline mask, cp.async 3-buffer pipeline ----
    {
        uint32_t db = t0;
        cp16(db + (sr0*KTS + sd)*4,        &k[(size_t)(b*SEQ + sr0) * QS + h*DHEAD + sd]);
        cp16(db + ((sr0+32)*KTS + sd)*4,   &k[(size_t)(b*SEQ + sr0+32) * QS + h*DHEAD + sd]);
        cp_commit();
    }
    for (int kt = 0; kt < 16; kt++) {
        if (kt + 1 < 16) {
            uint32_t db = t0 + ((kt+1)%3) * (TILE_F*4);
            int base = (kt+1)*64;
            cp16(db + (sr0*KTS + sd)*4,      &k[(size_t)(b*SEQ + base + sr0) * QS + h*DHEAD + sd]);
            cp16(db + ((sr0+32)*KTS + sd)*4, &k[(size_t)(b*SEQ + base + sr0+32) * QS + h*DHEAD + sd]);
            cp_commit();
            asm volatile("cp.async.wait_group 1;");
        } else {
            asm volatile("cp.async.wait_group 0;");
        }
        __syncthreads();

        const uint32_t tb = t0 + (kt%3) * (TILE_F*4);
        uint32_t bk[4][4];
        #pragma unroll
        for (int g = 0; g < 4; g++)
            ldsm4(bk[g], tb + n0*(KTS*4) + g*64 + b_off);
        float c4[4] = {0.f, 0.f, 0.f, 0.f};
        #pragma unroll
        for (int s = 0; s < 8; s++)
            mma_tf32(c4, aq[s], &bk[s >> 1][(s & 1) * 2]);

        int r0  = qh*16 + grp;
        int col = n0 + 2*thr;
        int gk  = kt*64 + col;
        bool ma0, ma1, mb0, mb1;
        mask2(mask, (size_t)(b*SEQ + q0 + r0) * SEQ + gk,     mode, ma0, ma1);
        mask2(mask, (size_t)(b*SEQ + q0 + r0 + 8) * SEQ + gk, mode, mb0, mb1);
        float s0 = ma0 ? -1e9f : c4[0] * 0.125f;
        float s1 = ma1 ? -1e9f : c4[1] * 0.125f;
        float s2 = mb0 ? -1e9f : c4[2] * 0.125f;
        float s3 = mb1 ? -1e9f : c4[3] * 0.125f;
        *(float2*)&scores[r0*SCS + gk]     = make_float2(s0, s1);
        *(float2*)&scores[(r0+8)*SCS + gk] = make_float2(s2, s3);
    }
    __syncthreads();

    // prefetch V[0] -> buf0 (overlaps softmax)
    {
        uint32_t db = t0;
        cp16(db + (sr0*KTS + sd)*4,        &v[(size_t)(b*SEQ + sr0) * QS + h*DHEAD + sd]);
        cp16(db + ((sr0+32)*KTS + sd)*4,   &v[(size_t)(b*SEQ + sr0+32) * QS + h*DHEAD + sd]);
        cp_commit();
    }

    // ---- phase 2: softmax (16 threads per row) ----
    {
        const int r = tid >> 4;
        const int t = tid & 15;
        float* row = &scores[r * SCS];
        float mx = -3.4e38f;
        for (int j = t; j < SEQ; j += 16) mx = fmaxf(mx, row[j]);
        #pragma unroll
        for (int m = 8; m; m >>= 1) mx = fmaxf(mx, __shfl_xor_sync(0xffffffffu, mx, m));
        float sum = 0.f;
        for (int j = t; j < SEQ; j += 16) {
            float e = __expf(row[j] - mx);
            row[j] = e;
            sum += e;
        }
        #pragma unroll
        for (int m = 8; m; m >>= 1) sum += __shfl_xor_sync(0xffffffffu, sum, m);
        if (t == 0) sinv[r] = 1.0f / sum;
    }
    __syncthreads();

    // ---- normalize, write attn exact, round probs in-place ----
    {
        float* dst = attn ? attn + ((size_t)(b*NHEADS + h) * SEQ + q0) * SEQ : nullptr;
        for (int i4 = tid; i4 < TQ*256; i4 += 512) {
            int r = i4 >> 8, c4i = i4 & 255;
            float iv = sinv[r];
            float4 w = *(float4*)&scores[r*SCS + c4i*4];
            w.x *= iv; w.y *= iv; w.z *= iv; w.w *= iv;
            if (dst) ((float4*)dst)[(size_t)r*256 + c4i] = w;
            w.x = rna(w.x); w.y = rna(w.y); w.z = rna(w.z); w.w = rna(w.w);
            *(float4*)&scores[r*SCS + c4i*4] = w;
        }
    }
    __syncthreads();

    // ---- phase 3: context = P @ V, cp.async pipelined V staging ----
    float cc[4] = {0.f, 0.f, 0.f, 0.f};
    for (int vt = 0; vt < 16; vt++) {
        if (vt + 1 < 16) {
            uint32_t db = t0 + ((vt+1)%3) * (TILE_F*4);
            int base = (vt+1)*64;
            cp16(db + (sr0*KTS + sd)*4,      &v[(size_t)(b*SEQ + base + sr0) * QS + h*DHEAD + sd]);
            cp16(db + ((sr0+32)*KTS + sd)*4, &v[(size_t)(b*SEQ + base + sr0+32) * QS + h*DHEAD + sd]);
            cp_commit();
            asm volatile("cp.async.wait_group 1;");
        } else {
            asm volatile("cp.async.wait_group 0;");
        }
        __syncthreads();

        const float* tbuf = tiles + (vt%3) * TILE_F;
        #pragma unroll
        for (int g = 0; g < 4; g++) {
            uint32_t ap0[4], ap1[4];
            ldsm4(ap0, sbase + (qh*16)*(SCS*4) + (vt*64 + g*16) * 4 + aS_off);
            ldsm4(ap1, sbase + (qh*16)*(SCS*4) + (vt*64 + g*16 + 8) * 4 + aS_off);
            int kloc0 = g*16;
            uint32_t bv0[2], bv1[2];
            bv0[0] = __float_as_uint(tbuf[(kloc0 + thr    )*KTS + n0 + grp]);
            bv0[1] = __float_as_uint(tbuf[(kloc0 + thr + 4)*KTS + n0 + grp]);
            bv1[0] = __float_as_uint(tbuf[(kloc0 + 8 + thr    )*KTS + n0 + grp]);
            bv1[1] = __float_as_uint(tbuf[(kloc0 + 8 + thr + 4)*KTS + n0 + grp]);
            mma_tf32(cc, ap0, bv0);
            mma_tf32(cc, ap1, bv1);
        }
    }
    {
        int dc = h*DHEAD + n0 + 2*thr;
        int r0 = q0 + qh*16 + grp;
        *(float2*)&ctx[(size_t)(b*SEQ + r0) * DMODEL + dc] =
            make_float2(rna(cc[0]), rna(cc[1]));
        *(float2*)&ctx[(size_t)(b*SEQ + r0 + 8) * DMODEL + dc] =
            make_float2(rna(cc[2]), rna(cc[3]));
    }
}

// ---------------- residual + LayerNorm (tf32-rounded out; feeds FFN1) ----------------
__global__ __launch_bounds__(256)
void ln_kernel(const float* __restrict__ proj, const float* __restrict__ x,
               const float* __restrict__ gamma, const float* __restrict__ beta,
               float* __restrict__ out) {
    const int row = blockIdx.x;
    const float* p  = proj + (size_t)row * DMODEL;
    const float* xr = x    + (size_t)row * DMODEL;
    float s = 0.f, s2 = 0.f;
    for (int i = threadIdx.x; i < DMODEL; i += 256) {
        float v = p[i] + xr[i];
        s += v; s2 += v*v;
    }
    #pragma unroll
    for (int m = 16; m; m >>= 1) {
        s  += __shfl_xor_sync(0xffffffffu, s,  m);
        s2 += __shfl_xor_sync(0xffffffffu, s2, m);
    }
    __shared__ float ws[8], ws2[8];
    int w = threadIdx.x >> 5, l = threadIdx.x & 31;
    if (l == 0) { ws[w] = s; ws2[w] = s2; }
    __syncthreads();
    __shared__ float smu, srstd;
    if (threadIdx.x == 0) {
        float ts = 0.f, ts2 = 0.f;
        for (int i = 0; i < 8; i++) { ts += ws[i]; ts2 += ws2[i]; }
        float mu  = ts  * (1.0f/DMODEL);
        float var = ts2 * (1.0f/DMODEL) - mu*mu;
        smu = mu; srstd = rsqrtf(var + LN_EPS);
    }
    __syncthreads();
    float mu = smu, r = srstd;
    float* o = out + (size_t)row * DMODEL;
    for (int i = threadIdx.x; i < DMODEL; i += 256)
        o[i] = rna((p[i] + xr[i] - mu) * r * gamma[i] + beta[i]);
}

// ---------------- launcher ----------------
extern "C" void kernel_launch(void* const* d_in, const int* in_sizes, int n_in,
                              void* d_out, int out_size) {
    const float* x     = (const float*)d_in[0];
    const void*  mask  = d_in[1];
    const float* Wq    = (const float*)d_in[2];
    const float* bq    = (const float*)d_in[3];
    const float* Wk    = (const float*)d_in[4];
    const float* bk    = (const float*)d_in[5];
    const float* Wv    = (const float*)d_in[6];
    const float* bv    = (const float*)d_in[7];
    const float* Wo    = (const float*)d_in[8];
    const float* bo    = (const float*)d_in[9];
    const float* gamma = (const float*)d_in[10];
    const float* beta  = (const float*)d_in[11];
    const float* W1    = (const float*)d_in[12];
    const float* b1    = (const float*)d_in[13];
    const float* W2    = (const float*)d_in[14];
    const float* b2    = (const float*)d_in[15];

    float* out = (float*)d_out;
    const long long FFN_E  = (long long)ROWS * DMODEL;
    const long long ATTN_E = (long long)BATCH * NHEADS * SEQ * SEQ;
    float* attn = ((long long)out_size >= FFN_E + ATTN_E) ? (out + FFN_E) : nullptr;

    float *qkv, *ctx, *prj, *ln, *mid, *xt, *wqkvt, *bqkv, *wot, *w1t, *w2t;
    cudaGetSymbolAddress((void**)&qkv,   g_qkv);
    cudaGetSymbolAddress((void**)&ctx,   g_ctx);
    cudaGetSymbolAddress((void**)&prj,   g_prj);
    cudaGetSymbolAddress((void**)&ln,    g_ln);
    cudaGetSymbolAddress((void**)&mid,   g_mid);
    cudaGetSymbolAddress((void**)&xt,    g_xt);
    cudaGetSymbolAddress((void**)&wqkvt, g_wqkvt);
    cudaGetSymbolAddress((void**)&bqkv,  g_bqkv);
    cudaGetSymbolAddress((void**)&wot,   g_wot);
    cudaGetSymbolAddress((void**)&w1t,   g_w1t);
    cudaGetSymbolAddress((void**)&w2t,   g_w2t);

    cudaFuncSetAttribute(attn_kernel, cudaFuncAttributeMaxDynamicSharedMemorySize, ATTN_SMEM);

    detect_mask_kernel<<<1, 32>>>((const unsigned char*)mask);
    round_tf32_kernel<<<1024, 256>>>(x, xt, ROWS*DMODEL);
    transpose_all_kernel<<<dim3(96, 96, 6), dim3(32, 8)>>>(Wq, Wk, Wv, Wo, W1, W2,
                                                           wqkvt, wot, w1t, w2t);
    pack_bias_kernel<<<3, 256>>>(bq, bk, bv, bqkv);
    gemm_tf32_kernel<<<dim3(QS/128, ROWS/128), 256>>>(xt, wqkvt, bqkv, qkv, ROWS, QS, DMODEL, 2);

    attn_kernel<<<dim3(SEQ/TQ, BATCH*NHEADS), 512, ATTN_SMEM>>>(qkv, mask, attn, ctx);

    gemm_tf32_kernel<<<dim3(DMODEL/128, ROWS/128), 256>>>(ctx, wot, bo, prj, ROWS, DMODEL, DMODEL, 0);
    ln_kernel<<<ROWS, 256>>>(prj, x, gamma, beta, ln);

    gemm_tf32_kernel<<<dim3(DFF/128, ROWS/128), 256>>>(ln, w1t, b1, mid, ROWS, DFF, DMODEL, 1);
    gemm_tf32_kernel<<<dim3(DMODEL/128, ROWS/128), 256>>>(mid, w2t, b2, out, ROWS, DMODEL, DFF, 0);
}